// round 7
// baseline (speedup 1.0000x reference)
#include <cuda_runtime.h>
#include <cstdint>

// Problem constants: B=2, T=2048, C=1024, H=16, D=64
#define TT 2048

// Scratch (allocation-free rule: __device__ globals)
__device__ float g_qkv[2 * 2048 * 3 * 1024];  // [B,T,3,H,D]
__device__ float g_y[2 * 2048 * 1024];        // [B,T,H,D]

__device__ __forceinline__ uint32_t f2tf32(float f) {
    uint32_t r;
    asm("cvt.rna.tf32.f32 %0, %1;" : "=r"(r) : "f"(f));
    return r;
}

__device__ __forceinline__ void mma_tf32(float* c, const uint32_t* a, const uint32_t* b) {
    asm volatile(
        "mma.sync.aligned.m16n8k8.row.col.f32.tf32.tf32.f32 "
        "{%0,%1,%2,%3}, {%4,%5,%6,%7}, {%8,%9}, {%0,%1,%2,%3};\n"
        : "+f"(c[0]), "+f"(c[1]), "+f"(c[2]), "+f"(c[3])
        : "r"(a[0]), "r"(a[1]), "r"(a[2]), "r"(a[3]), "r"(b[0]), "r"(b[1]));
}

#define CP_ASYNC16(dst_u32, src) \
    asm volatile("cp.async.cg.shared.global [%0], [%1], 16;\n" :: "r"(dst_u32), "l"(src))
#define CP_COMMIT() asm volatile("cp.async.commit_group;\n" ::: "memory")
#define CP_WAIT0()  asm volatile("cp.async.wait_group 0;\n" ::: "memory")

// ---------------------------------------------------------------------------
// TF32 tensor-core GEMM with bias, 2-stage smem double buffer (unchanged).
// ---------------------------------------------------------------------------
#define PADK 20
#define PADN 136

__global__ __launch_bounds__(256, 2)
void tf32_gemm_bias(const float* __restrict__ A, const float* __restrict__ Bw,
                    const float* __restrict__ bias, float* __restrict__ Cout,
                    int M, int N, int K) {
    __shared__ uint32_t As[2][128 * PADK];
    __shared__ uint32_t Bs[2][16 * PADN];

    const int tid = threadIdx.x;
    const int lane = tid & 31;
    const int warp = tid >> 5;
    const int gid = lane >> 2;
    const int tig = lane & 3;
    const int wm = warp >> 1;
    const int wn = warp & 1;
    const int m0w = wm * 32;
    const int n0w = wn * 64;
    const int br = blockIdx.y * 128;
    const int bc = blockIdx.x * 128;

    const int arow = tid >> 2;
    const int akc  = (tid & 3) * 4;
    const int bkr  = tid >> 5;
    const int bnc  = (tid & 31) * 4;

    const float* Ap0 = A + (long)(br + arow) * K + akc;
    const float* Ap1 = A + (long)(br + arow + 64) * K + akc;
    const float* Bp0 = Bw + (long)bkr * N + bc + bnc;
    const float* Bp1 = Bw + (long)(bkr + 8) * N + bc + bnc;

    float c[2][8][4];
#pragma unroll
    for (int mi = 0; mi < 2; mi++)
#pragma unroll
        for (int nj = 0; nj < 8; nj++)
#pragma unroll
            for (int e = 0; e < 4; e++) c[mi][nj][e] = 0.f;

    float4 ag0 = *(const float4*)(Ap0);
    float4 ag1 = *(const float4*)(Ap1);
    float4 bg0 = *(const float4*)(Bp0);
    float4 bg1 = *(const float4*)(Bp1);
    {
        uint4 s;
        s.x = f2tf32(ag0.x); s.y = f2tf32(ag0.y); s.z = f2tf32(ag0.z); s.w = f2tf32(ag0.w);
        *(uint4*)&As[0][arow * PADK + akc] = s;
        s.x = f2tf32(ag1.x); s.y = f2tf32(ag1.y); s.z = f2tf32(ag1.z); s.w = f2tf32(ag1.w);
        *(uint4*)&As[0][(arow + 64) * PADK + akc] = s;
        s.x = f2tf32(bg0.x); s.y = f2tf32(bg0.y); s.z = f2tf32(bg0.z); s.w = f2tf32(bg0.w);
        *(uint4*)&Bs[0][bkr * PADN + bnc] = s;
        s.x = f2tf32(bg1.x); s.y = f2tf32(bg1.y); s.z = f2tf32(bg1.z); s.w = f2tf32(bg1.w);
        *(uint4*)&Bs[0][(bkr + 8) * PADN + bnc] = s;
    }
    __syncthreads();

    int st = 0;
    for (int k0 = 0; k0 < K; k0 += 16) {
        const bool hasNext = (k0 + 16 < K);
        if (hasNext) {
            ag0 = *(const float4*)(Ap0 + k0 + 16);
            ag1 = *(const float4*)(Ap1 + k0 + 16);
            bg0 = *(const float4*)(Bp0 + (long)(k0 + 16) * N);
            bg1 = *(const float4*)(Bp1 + (long)(k0 + 16) * N);
        }

#pragma unroll
        for (int ks = 0; ks < 16; ks += 8) {
            uint32_t a[2][4];
#pragma unroll
            for (int mi = 0; mi < 2; mi++) {
                int base = (m0w + mi * 16 + gid) * PADK + ks + tig;
                a[mi][0] = As[st][base];
                a[mi][1] = As[st][base + 8 * PADK];
                a[mi][2] = As[st][base + 4];
                a[mi][3] = As[st][base + 8 * PADK + 4];
            }
            uint32_t b[8][2];
#pragma unroll
            for (int nj = 0; nj < 8; nj++) {
                int base = (ks + tig) * PADN + n0w + nj * 8 + gid;
                b[nj][0] = Bs[st][base];
                b[nj][1] = Bs[st][base + 4 * PADN];
            }
#pragma unroll
            for (int mi = 0; mi < 2; mi++)
#pragma unroll
                for (int nj = 0; nj < 8; nj++)
                    mma_tf32(c[mi][nj], a[mi], b[nj]);
        }

        if (hasNext) {
            uint4 s;
            s.x = f2tf32(ag0.x); s.y = f2tf32(ag0.y); s.z = f2tf32(ag0.z); s.w = f2tf32(ag0.w);
            *(uint4*)&As[st ^ 1][arow * PADK + akc] = s;
            s.x = f2tf32(ag1.x); s.y = f2tf32(ag1.y); s.z = f2tf32(ag1.z); s.w = f2tf32(ag1.w);
            *(uint4*)&As[st ^ 1][(arow + 64) * PADK + akc] = s;
            s.x = f2tf32(bg0.x); s.y = f2tf32(bg0.y); s.z = f2tf32(bg0.z); s.w = f2tf32(bg0.w);
            *(uint4*)&Bs[st ^ 1][bkr * PADN + bnc] = s;
            s.x = f2tf32(bg1.x); s.y = f2tf32(bg1.y); s.z = f2tf32(bg1.z); s.w = f2tf32(bg1.w);
            *(uint4*)&Bs[st ^ 1][(bkr + 8) * PADN + bnc] = s;
        }
        __syncthreads();
        st ^= 1;
    }

#pragma unroll
    for (int mi = 0; mi < 2; mi++) {
        int row = br + m0w + mi * 16 + gid;
#pragma unroll
        for (int nj = 0; nj < 8; nj++) {
            int col = bc + n0w + nj * 8 + tig * 2;
            float2 bb = *(const float2*)(bias + col);
            float2 o0 = make_float2(c[mi][nj][0] + bb.x, c[mi][nj][1] + bb.y);
            float2 o1 = make_float2(c[mi][nj][2] + bb.x, c[mi][nj][3] + bb.y);
            *(float2*)(Cout + (long)row * N + col) = o0;
            *(float2*)(Cout + (long)(row + 8) * N + col) = o1;
        }
    }
}

// ---------------------------------------------------------------------------
// Fused per-head RMSNorm + RoPE on q and k slots of g_qkv (in place).
// ---------------------------------------------------------------------------
__global__ __launch_bounds__(256)
void norm_rope_kernel(float* __restrict__ qkv,
                      const float* __restrict__ cosb,
                      const float* __restrict__ sinb) {
    __shared__ float qn[1024];
    __shared__ float kn[1024];
    const int bt = blockIdx.x;
    const int t = bt & (TT - 1);
    const int tid = threadIdx.x;
    float* qrow = qkv + (long)bt * 3072;
    float* krow = qrow + 1024;

    float4 qv = *(const float4*)(qrow + tid * 4);
    float4 kv = *(const float4*)(krow + tid * 4);
    float qs = qv.x * qv.x + qv.y * qv.y + qv.z * qv.z + qv.w * qv.w;
    float ks = kv.x * kv.x + kv.y * kv.y + kv.z * kv.z + kv.w * kv.w;
#pragma unroll
    for (int o = 8; o > 0; o >>= 1) {
        qs += __shfl_xor_sync(0xffffffffu, qs, o);
        ks += __shfl_xor_sync(0xffffffffu, ks, o);
    }
    const float qsc = rsqrtf(qs * (1.f / 64.f) + 1.1920929e-07f);
    const float ksc = rsqrtf(ks * (1.f / 64.f) + 1.1920929e-07f);
    float4 qn4 = make_float4(qv.x * qsc, qv.y * qsc, qv.z * qsc, qv.w * qsc);
    float4 kn4 = make_float4(kv.x * ksc, kv.y * ksc, kv.z * ksc, kv.w * ksc);
    *(float4*)&qn[tid * 4] = qn4;
    *(float4*)&kn[tid * 4] = kn4;
    __syncthreads();

    const int i = tid * 4;
    const int d = i & 63;
    const int base = i - d;
    float4 cv = *(const float4*)(cosb + t * 64 + d);
    float4 sv = *(const float4*)(sinb + t * 64 + d);
    float4 rq, rk;
    if (d < 32) {
        float4 pq = *(const float4*)&qn[base + d + 32];
        float4 pk = *(const float4*)&kn[base + d + 32];
        rq = make_float4(-pq.x, -pq.y, -pq.z, -pq.w);
        rk = make_float4(-pk.x, -pk.y, -pk.z, -pk.w);
    } else {
        rq = *(const float4*)&qn[base + d - 32];
        rk = *(const float4*)&kn[base + d - 32];
    }
    float4 oq, ok;
    oq.x = qn4.x * cv.x + rq.x * sv.x;  oq.y = qn4.y * cv.y + rq.y * sv.y;
    oq.z = qn4.z * cv.z + rq.z * sv.z;  oq.w = qn4.w * cv.w + rq.w * sv.w;
    ok.x = kn4.x * cv.x + rk.x * sv.x;  ok.y = kn4.y * cv.y + rk.y * sv.y;
    ok.z = kn4.z * cv.z + rk.z * sv.z;  ok.w = kn4.w * cv.w + rk.w * sv.w;
    *(float4*)(qrow + i) = oq;
    *(float4*)(krow + i) = ok;
}

// ---------------------------------------------------------------------------
// TF32 flash attention, cp.async double-buffered K/V.
// BQ=128, BKV=64, 8 warps, warp = 16 rows x 64 kv cols. 2 CTAs/SM.
// K/V enter mma truncated (no cvt) — error budget analyzed in commit msg.
// ---------------------------------------------------------------------------
#define KPAD 68    // K frag lanes: 4*gid + tig -> all 32 banks
#define VPAD 72    // V frag lanes: 8*tig + gid -> all 32 banks
#define PPAD 68
#define ATT_SMEM ((2 * (64 * KPAD + 64 * VPAD) + 128 * PPAD) * 4)

__global__ __launch_bounds__(256, 2)
void attn_tf32_kernel(const float* __restrict__ qkv, float* __restrict__ y) {
    extern __shared__ uint32_t smu[];
    uint32_t* Ks[2] = {smu, smu + 64 * KPAD};
    uint32_t* Vs[2] = {smu + 2 * 64 * KPAD, smu + 2 * 64 * KPAD + 64 * VPAD};
    uint32_t* Ps = smu + 2 * (64 * KPAD + 64 * VPAD);  // [128][PPAD]; also Q staging

    const int qb = (int)(gridDim.x - 1) - (int)blockIdx.x;  // heavy CTAs first
    const int h = blockIdx.y, b = blockIdx.z;
    const int tid = threadIdx.x;
    const int lane = tid & 31, warp = tid >> 5;
    const int gid = lane >> 2, tig = lane & 3;
    const int r0 = warp * 16;

    // cp.async source/dst mapping: row = tid>>2, dh = (tid&3)*16
    const int cprow = tid >> 2;
    const int cpdh = (tid & 3) * 16;
    const long kvbase = (long)(b * TT + cprow) * 3072 + h * 64 + cpdh;
    const uint32_t ksm[2] = {
        (uint32_t)__cvta_generic_to_shared(&Ks[0][cprow * KPAD + cpdh]),
        (uint32_t)__cvta_generic_to_shared(&Ks[1][cprow * KPAD + cpdh])};
    const uint32_t vsm[2] = {
        (uint32_t)__cvta_generic_to_shared(&Vs[0][cprow * VPAD + cpdh]),
        (uint32_t)__cvta_generic_to_shared(&Vs[1][cprow * VPAD + cpdh])};

    // ---- Issue cp.async for KV tile 0 into stage 0 (overlaps Q staging) ----
    {
        const float* ksrc = qkv + kvbase + 1024;
        const float* vsrc = qkv + kvbase + 2048;
#pragma unroll
        for (int j = 0; j < 4; j++) {
            CP_ASYNC16(ksm[0] + j * 16, ksrc + j * 4);
            CP_ASYNC16(vsm[0] + j * 16, vsrc + j * 4);
        }
        CP_COMMIT();
    }

    // ---- Stage Q (scaled, tf32-rna) into Ps, load A-fragments ----
    {
        const int row = tid >> 1;
        const int dh = (tid & 1) * 32;
        const float* src = qkv + ((long)(b * TT + qb * 128 + row) * 3) * 1024 + h * 64 + dh;
#pragma unroll
        for (int j = 0; j < 8; j++) {
            float4 v = *(const float4*)(src + j * 4);
            uint4 s;
            s.x = f2tf32(v.x * 0.125f); s.y = f2tf32(v.y * 0.125f);
            s.z = f2tf32(v.z * 0.125f); s.w = f2tf32(v.w * 0.125f);
            *(uint4*)&Ps[row * PPAD + dh + j * 4] = s;
        }
    }
    __syncthreads();
    uint32_t qa[8][4];
#pragma unroll
    for (int ks = 0; ks < 8; ks++) {
        int base = (r0 + gid) * PPAD + ks * 8 + tig;
        qa[ks][0] = Ps[base];
        qa[ks][1] = Ps[base + 8 * PPAD];
        qa[ks][2] = Ps[base + 4];
        qa[ks][3] = Ps[base + 8 * PPAD + 4];
    }

    float cO[8][4];
#pragma unroll
    for (int nj = 0; nj < 8; nj++)
#pragma unroll
        for (int e = 0; e < 4; e++) cO[nj][e] = 0.f;
    float mrow0 = -3.0e38f, mrow1 = -3.0e38f, lrow0 = 0.f, lrow1 = 0.f;

    const int nkv = 2 * (qb + 1);
    int st = 0;
    for (int kb = 0; kb < nkv; kb++) {
        CP_WAIT0();        // tile kb's copies (this thread) complete
        __syncthreads();   // all threads' copies visible; prev iter fully done

        // Issue cp.async for tile kb+1 into the other stage (overlaps math)
        if (kb + 1 < nkv) {
            const float* ksrc = qkv + kvbase + (long)(kb + 1) * 64 * 3072 + 1024;
            const float* vsrc = ksrc + 1024;
#pragma unroll
            for (int j = 0; j < 4; j++) {
                CP_ASYNC16(ksm[st ^ 1] + j * 16, ksrc + j * 4);
                CP_ASYNC16(vsm[st ^ 1] + j * 16, vsrc + j * 4);
            }
            CP_COMMIT();
        }

        const uint32_t* Kc = Ks[st];
        const uint32_t* Vc = Vs[st];

        // ---- S = Q @ K^T : warp computes 16 rows x 64 cols (8 n-tiles) ----
        float cS[8][4];
#pragma unroll
        for (int nj = 0; nj < 8; nj++)
#pragma unroll
            for (int e = 0; e < 4; e++) cS[nj][e] = 0.f;

#pragma unroll
        for (int ks = 0; ks < 8; ks++) {
#pragma unroll
            for (int nj = 0; nj < 8; nj++) {
                uint32_t bb[2];
                int base = (nj * 8 + gid) * KPAD + ks * 8 + tig;
                bb[0] = Kc[base];
                bb[1] = Kc[base + 4];
                mma_tf32(cS[nj], qa[ks], bb);
            }
        }

        if (kb >= 2 * qb) {  // tiles intersecting the causal diagonal
            int rA = qb * 128 + r0 + gid;
            int rB = rA + 8;
#pragma unroll
            for (int nj = 0; nj < 8; nj++) {
                int col = kb * 64 + nj * 8 + 2 * tig;
                if (col     > rA) cS[nj][0] = -3.0e38f;
                if (col + 1 > rA) cS[nj][1] = -3.0e38f;
                if (col     > rB) cS[nj][2] = -3.0e38f;
                if (col + 1 > rB) cS[nj][3] = -3.0e38f;
            }
        }

        // ---- Online softmax (2 rows per thread; reduce over 4 tig lanes) ----
        float mx0 = -3.0e38f, mx1 = -3.0e38f;
#pragma unroll
        for (int nj = 0; nj < 8; nj++) {
            mx0 = fmaxf(mx0, fmaxf(cS[nj][0], cS[nj][1]));
            mx1 = fmaxf(mx1, fmaxf(cS[nj][2], cS[nj][3]));
        }
        mx0 = fmaxf(mx0, __shfl_xor_sync(0xffffffffu, mx0, 1));
        mx0 = fmaxf(mx0, __shfl_xor_sync(0xffffffffu, mx0, 2));
        mx1 = fmaxf(mx1, __shfl_xor_sync(0xffffffffu, mx1, 1));
        mx1 = fmaxf(mx1, __shfl_xor_sync(0xffffffffu, mx1, 2));
        float mn0 = fmaxf(mrow0, mx0), mn1 = fmaxf(mrow1, mx1);
        float a0 = __expf(mrow0 - mn0), a1 = __expf(mrow1 - mn1);
        mrow0 = mn0; mrow1 = mn1;
        float s0 = 0.f, s1 = 0.f;
#pragma unroll
        for (int nj = 0; nj < 8; nj++) {
            cS[nj][0] = __expf(cS[nj][0] - mn0); s0 += cS[nj][0];
            cS[nj][1] = __expf(cS[nj][1] - mn0); s0 += cS[nj][1];
            cS[nj][2] = __expf(cS[nj][2] - mn1); s1 += cS[nj][2];
            cS[nj][3] = __expf(cS[nj][3] - mn1); s1 += cS[nj][3];
        }
        s0 += __shfl_xor_sync(0xffffffffu, s0, 1);
        s0 += __shfl_xor_sync(0xffffffffu, s0, 2);
        s1 += __shfl_xor_sync(0xffffffffu, s1, 1);
        s1 += __shfl_xor_sync(0xffffffffu, s1, 2);
        lrow0 = lrow0 * a0 + s0;
        lrow1 = lrow1 * a1 + s1;
#pragma unroll
        for (int nj = 0; nj < 8; nj++) {
            cO[nj][0] *= a0; cO[nj][1] *= a0;
            cO[nj][2] *= a1; cO[nj][3] *= a1;
        }

        // ---- Store P (tf32-rna); warp-private rows ----
#pragma unroll
        for (int nj = 0; nj < 8; nj++) {
            int col = nj * 8 + 2 * tig;
            uint2 p0 = make_uint2(f2tf32(cS[nj][0]), f2tf32(cS[nj][1]));
            *(uint2*)&Ps[(r0 + gid) * PPAD + col] = p0;
            uint2 p1 = make_uint2(f2tf32(cS[nj][2]), f2tf32(cS[nj][3]));
            *(uint2*)&Ps[(r0 + gid + 8) * PPAD + col] = p1;
        }
        __syncwarp();

        // ---- O += P @ V : 16 rows x 64 dims (8 n-tiles), 8 k-steps ----
#pragma unroll
        for (int ks = 0; ks < 8; ks++) {
            uint32_t pa[4];
            int abase = (r0 + gid) * PPAD + ks * 8 + tig;
            pa[0] = Ps[abase];
            pa[1] = Ps[abase + 8 * PPAD];
            pa[2] = Ps[abase + 4];
            pa[3] = Ps[abase + 8 * PPAD + 4];
#pragma unroll
            for (int nj = 0; nj < 8; nj++) {
                uint32_t bb[2];
                int bbase = (ks * 8 + tig) * VPAD + nj * 8 + gid;
                bb[0] = Vc[bbase];
                bb[1] = Vc[bbase + 4 * VPAD];
                mma_tf32(cO[nj], pa, bb);
            }
        }
        st ^= 1;
    }

    // ---- Epilogue ----
    float inv0 = 1.0f / lrow0, inv1 = 1.0f / lrow1;
    long rowA = (long)(b * TT + qb * 128 + r0 + gid) * 1024 + h * 64;
    long rowB = rowA + 8 * 1024;
#pragma unroll
    for (int nj = 0; nj < 8; nj++) {
        int col = nj * 8 + 2 * tig;
        *(float2*)(y + rowA + col) = make_float2(cO[nj][0] * inv0, cO[nj][1] * inv0);
        *(float2*)(y + rowB + col) = make_float2(cO[nj][2] * inv1, cO[nj][3] * inv1);
    }
}

// ---------------------------------------------------------------------------
extern "C" void kernel_launch(void* const* d_in, const int* in_sizes, int n_in,
                              void* d_out, int out_size) {
    const float* x      = (const float*)d_in[0];
    const float* cosb   = (const float*)d_in[1];
    const float* sinb   = (const float*)d_in[2];
    const float* W_attn = (const float*)d_in[3];
    const float* b_attn = (const float*)d_in[4];
    const float* W_proj = (const float*)d_in[5];
    const float* b_proj = (const float*)d_in[6];
    float* out = (float*)d_out;

    float *qkv, *y;
    cudaGetSymbolAddress((void**)&qkv, g_qkv);
    cudaGetSymbolAddress((void**)&y, g_y);

    // 1) QKV GEMM (TF32, double-buffered): [4096,1024] @ [1024,3072] + bias
    tf32_gemm_bias<<<dim3(3072 / 128, 4096 / 128), 256>>>(x, W_attn, b_attn, qkv, 4096, 3072, 1024);

    // 2) per-head RMSNorm + RoPE on q,k (in place)
    norm_rope_kernel<<<2 * TT, 256>>>(qkv, cosb, sinb);

    // 3) causal flash attention (TF32, cp.async double-buffered KV)
    cudaFuncSetAttribute(attn_tf32_kernel, cudaFuncAttributeMaxDynamicSharedMemorySize, ATT_SMEM);
    attn_tf32_kernel<<<dim3(TT / 128, 16, 2), 256, ATT_SMEM>>>(qkv, y);

    // 4) output projection (TF32, double-buffered): [4096,1024] @ [1024,1024] + bias
    tf32_gemm_bias<<<dim3(1024 / 128, 4096 / 128), 256>>>(y, W_proj, b_proj, out, 4096, 1024, 1024);
}

// round 8
// speedup vs baseline: 1.0451x; 1.0451x over previous
#include <cuda_runtime.h>
#include <cstdint>

// Problem constants: B=2, T=2048, C=1024, H=16, D=64
#define TT 2048

// Scratch (allocation-free rule: __device__ globals)
__device__ float g_qkv[2 * 2048 * 3 * 1024];  // [B,T,3,H,D]
__device__ float g_y[2 * 2048 * 1024];        // [B,T,H,D]

__device__ __forceinline__ uint32_t f2tf32(float f) {
    uint32_t r;
    asm("cvt.rna.tf32.f32 %0, %1;" : "=r"(r) : "f"(f));
    return r;
}

__device__ __forceinline__ void mma_tf32(float* c, const uint32_t* a, const uint32_t* b) {
    asm volatile(
        "mma.sync.aligned.m16n8k8.row.col.f32.tf32.tf32.f32 "
        "{%0,%1,%2,%3}, {%4,%5,%6,%7}, {%8,%9}, {%0,%1,%2,%3};\n"
        : "+f"(c[0]), "+f"(c[1]), "+f"(c[2]), "+f"(c[3])
        : "r"(a[0]), "r"(a[1]), "r"(a[2]), "r"(a[3]), "r"(b[0]), "r"(b[1]));
}

// ---------------------------------------------------------------------------
// TF32 tensor-core GEMM with bias, 2-stage smem double buffer (round-6).
// ---------------------------------------------------------------------------
#define PADK 20
#define PADN 136

__global__ __launch_bounds__(256, 2)
void tf32_gemm_bias(const float* __restrict__ A, const float* __restrict__ Bw,
                    const float* __restrict__ bias, float* __restrict__ Cout,
                    int M, int N, int K) {
    __shared__ uint32_t As[2][128 * PADK];
    __shared__ uint32_t Bs[2][16 * PADN];

    const int tid = threadIdx.x;
    const int lane = tid & 31;
    const int warp = tid >> 5;
    const int gid = lane >> 2;
    const int tig = lane & 3;
    const int wm = warp >> 1;
    const int wn = warp & 1;
    const int m0w = wm * 32;
    const int n0w = wn * 64;
    const int br = blockIdx.y * 128;
    const int bc = blockIdx.x * 128;

    const int arow = tid >> 2;
    const int akc  = (tid & 3) * 4;
    const int bkr  = tid >> 5;
    const int bnc  = (tid & 31) * 4;

    const float* Ap0 = A + (long)(br + arow) * K + akc;
    const float* Ap1 = A + (long)(br + arow + 64) * K + akc;
    const float* Bp0 = Bw + (long)bkr * N + bc + bnc;
    const float* Bp1 = Bw + (long)(bkr + 8) * N + bc + bnc;

    float c[2][8][4];
#pragma unroll
    for (int mi = 0; mi < 2; mi++)
#pragma unroll
        for (int nj = 0; nj < 8; nj++)
#pragma unroll
            for (int e = 0; e < 4; e++) c[mi][nj][e] = 0.f;

    float4 ag0 = *(const float4*)(Ap0);
    float4 ag1 = *(const float4*)(Ap1);
    float4 bg0 = *(const float4*)(Bp0);
    float4 bg1 = *(const float4*)(Bp1);
    {
        uint4 s;
        s.x = f2tf32(ag0.x); s.y = f2tf32(ag0.y); s.z = f2tf32(ag0.z); s.w = f2tf32(ag0.w);
        *(uint4*)&As[0][arow * PADK + akc] = s;
        s.x = f2tf32(ag1.x); s.y = f2tf32(ag1.y); s.z = f2tf32(ag1.z); s.w = f2tf32(ag1.w);
        *(uint4*)&As[0][(arow + 64) * PADK + akc] = s;
        s.x = f2tf32(bg0.x); s.y = f2tf32(bg0.y); s.z = f2tf32(bg0.z); s.w = f2tf32(bg0.w);
        *(uint4*)&Bs[0][bkr * PADN + bnc] = s;
        s.x = f2tf32(bg1.x); s.y = f2tf32(bg1.y); s.z = f2tf32(bg1.z); s.w = f2tf32(bg1.w);
        *(uint4*)&Bs[0][(bkr + 8) * PADN + bnc] = s;
    }
    __syncthreads();

    int st = 0;
    for (int k0 = 0; k0 < K; k0 += 16) {
        const bool hasNext = (k0 + 16 < K);
        if (hasNext) {
            ag0 = *(const float4*)(Ap0 + k0 + 16);
            ag1 = *(const float4*)(Ap1 + k0 + 16);
            bg0 = *(const float4*)(Bp0 + (long)(k0 + 16) * N);
            bg1 = *(const float4*)(Bp1 + (long)(k0 + 16) * N);
        }

#pragma unroll
        for (int ks = 0; ks < 16; ks += 8) {
            uint32_t a[2][4];
#pragma unroll
            for (int mi = 0; mi < 2; mi++) {
                int base = (m0w + mi * 16 + gid) * PADK + ks + tig;
                a[mi][0] = As[st][base];
                a[mi][1] = As[st][base + 8 * PADK];
                a[mi][2] = As[st][base + 4];
                a[mi][3] = As[st][base + 8 * PADK + 4];
            }
            uint32_t b[8][2];
#pragma unroll
            for (int nj = 0; nj < 8; nj++) {
                int base = (ks + tig) * PADN + n0w + nj * 8 + gid;
                b[nj][0] = Bs[st][base];
                b[nj][1] = Bs[st][base + 4 * PADN];
            }
#pragma unroll
            for (int mi = 0; mi < 2; mi++)
#pragma unroll
                for (int nj = 0; nj < 8; nj++)
                    mma_tf32(c[mi][nj], a[mi], b[nj]);
        }

        if (hasNext) {
            uint4 s;
            s.x = f2tf32(ag0.x); s.y = f2tf32(ag0.y); s.z = f2tf32(ag0.z); s.w = f2tf32(ag0.w);
            *(uint4*)&As[st ^ 1][arow * PADK + akc] = s;
            s.x = f2tf32(ag1.x); s.y = f2tf32(ag1.y); s.z = f2tf32(ag1.z); s.w = f2tf32(ag1.w);
            *(uint4*)&As[st ^ 1][(arow + 64) * PADK + akc] = s;
            s.x = f2tf32(bg0.x); s.y = f2tf32(bg0.y); s.z = f2tf32(bg0.z); s.w = f2tf32(bg0.w);
            *(uint4*)&Bs[st ^ 1][bkr * PADN + bnc] = s;
            s.x = f2tf32(bg1.x); s.y = f2tf32(bg1.y); s.z = f2tf32(bg1.z); s.w = f2tf32(bg1.w);
            *(uint4*)&Bs[st ^ 1][(bkr + 8) * PADN + bnc] = s;
        }
        __syncthreads();
        st ^= 1;
    }

#pragma unroll
    for (int mi = 0; mi < 2; mi++) {
        int row = br + m0w + mi * 16 + gid;
#pragma unroll
        for (int nj = 0; nj < 8; nj++) {
            int col = bc + n0w + nj * 8 + tig * 2;
            float2 bb = *(const float2*)(bias + col);
            float2 o0 = make_float2(c[mi][nj][0] + bb.x, c[mi][nj][1] + bb.y);
            float2 o1 = make_float2(c[mi][nj][2] + bb.x, c[mi][nj][3] + bb.y);
            *(float2*)(Cout + (long)row * N + col) = o0;
            *(float2*)(Cout + (long)(row + 8) * N + col) = o1;
        }
    }
}

// ---------------------------------------------------------------------------
// Fused per-head RMSNorm + RoPE on q and k slots of g_qkv (in place).
// ---------------------------------------------------------------------------
__global__ __launch_bounds__(256)
void norm_rope_kernel(float* __restrict__ qkv,
                      const float* __restrict__ cosb,
                      const float* __restrict__ sinb) {
    __shared__ float qn[1024];
    __shared__ float kn[1024];
    const int bt = blockIdx.x;
    const int t = bt & (TT - 1);
    const int tid = threadIdx.x;
    float* qrow = qkv + (long)bt * 3072;
    float* krow = qrow + 1024;

    float4 qv = *(const float4*)(qrow + tid * 4);
    float4 kv = *(const float4*)(krow + tid * 4);
    float qs = qv.x * qv.x + qv.y * qv.y + qv.z * qv.z + qv.w * qv.w;
    float ks = kv.x * kv.x + kv.y * kv.y + kv.z * kv.z + kv.w * kv.w;
#pragma unroll
    for (int o = 8; o > 0; o >>= 1) {
        qs += __shfl_xor_sync(0xffffffffu, qs, o);
        ks += __shfl_xor_sync(0xffffffffu, ks, o);
    }
    const float qsc = rsqrtf(qs * (1.f / 64.f) + 1.1920929e-07f);
    const float ksc = rsqrtf(ks * (1.f / 64.f) + 1.1920929e-07f);
    float4 qn4 = make_float4(qv.x * qsc, qv.y * qsc, qv.z * qsc, qv.w * qsc);
    float4 kn4 = make_float4(kv.x * ksc, kv.y * ksc, kv.z * ksc, kv.w * ksc);
    *(float4*)&qn[tid * 4] = qn4;
    *(float4*)&kn[tid * 4] = kn4;
    __syncthreads();

    const int i = tid * 4;
    const int d = i & 63;
    const int base = i - d;
    float4 cv = *(const float4*)(cosb + t * 64 + d);
    float4 sv = *(const float4*)(sinb + t * 64 + d);
    float4 rq, rk;
    if (d < 32) {
        float4 pq = *(const float4*)&qn[base + d + 32];
        float4 pk = *(const float4*)&kn[base + d + 32];
        rq = make_float4(-pq.x, -pq.y, -pq.z, -pq.w);
        rk = make_float4(-pk.x, -pk.y, -pk.z, -pk.w);
    } else {
        rq = *(const float4*)&qn[base + d - 32];
        rk = *(const float4*)&kn[base + d - 32];
    }
    float4 oq, ok;
    oq.x = qn4.x * cv.x + rq.x * sv.x;  oq.y = qn4.y * cv.y + rq.y * sv.y;
    oq.z = qn4.z * cv.z + rq.z * sv.z;  oq.w = qn4.w * cv.w + rq.w * sv.w;
    ok.x = kn4.x * cv.x + rk.x * sv.x;  ok.y = kn4.y * cv.y + rk.y * sv.y;
    ok.z = kn4.z * cv.z + rk.z * sv.z;  ok.w = kn4.w * cv.w + rk.w * sv.w;
    *(float4*)(qrow + i) = oq;
    *(float4*)(krow + i) = ok;
}

// ---------------------------------------------------------------------------
// TF32 flash attention: 128-thread CTAs, 4 warps, warp tile 32q x 64kv.
// Each K/V fragment feeds 2 mmas (B-reuse over mi) -> crossbar bytes/mma
// halved vs the 16-row warp tile. Q in registers; 2 CTAs/SM.
// ---------------------------------------------------------------------------
#define KPAD 68    // K frag lanes: 4*gid + tig -> all 32 banks
#define VPAD 72    // V frag lanes: 8*tig + gid -> all 32 banks
#define PPAD 68
#define ATT_SMEM ((64 * KPAD + 64 * VPAD + 128 * PPAD) * 4)

__global__ __launch_bounds__(128, 2)
void attn_tf32_kernel(const float* __restrict__ qkv, float* __restrict__ y) {
    extern __shared__ uint32_t smu[];
    uint32_t* Ks = smu;                 // [64][KPAD]
    uint32_t* Vs = Ks + 64 * KPAD;      // [64][VPAD]
    uint32_t* Ps = Vs + 64 * VPAD;      // [128][PPAD]; also Q staging

    const int qb = (int)(gridDim.x - 1) - (int)blockIdx.x;  // heavy CTAs first
    const int h = blockIdx.y, b = blockIdx.z;
    const int tid = threadIdx.x;
    const int lane = tid & 31, warp = tid >> 5;
    const int gid = lane >> 2, tig = lane & 3;
    const int r0 = warp * 32;   // warp's 32 rows within the 128-row tile

    // ---- Stage Q (scaled, tf32-rna) into Ps, then load A-fragments ----
    {
        const int row = tid;    // 128 threads, one row each, 16 float4
        const float* src = qkv + ((long)(b * TT + qb * 128 + row) * 3) * 1024 + h * 64;
#pragma unroll
        for (int j = 0; j < 16; j++) {
            float4 v = *(const float4*)(src + j * 4);
            uint4 s;
            s.x = f2tf32(v.x * 0.125f); s.y = f2tf32(v.y * 0.125f);
            s.z = f2tf32(v.z * 0.125f); s.w = f2tf32(v.w * 0.125f);
            *(uint4*)&Ps[row * PPAD + j * 4] = s;
        }
    }
    __syncthreads();
    uint32_t qa[8][2][4];
#pragma unroll
    for (int ks = 0; ks < 8; ks++)
#pragma unroll
        for (int mi = 0; mi < 2; mi++) {
            int base = (r0 + mi * 16 + gid) * PPAD + ks * 8 + tig;
            qa[ks][mi][0] = Ps[base];
            qa[ks][mi][1] = Ps[base + 8 * PPAD];
            qa[ks][mi][2] = Ps[base + 4];
            qa[ks][mi][3] = Ps[base + 8 * PPAD + 4];
        }

    float cO[2][8][4];
#pragma unroll
    for (int mi = 0; mi < 2; mi++)
#pragma unroll
        for (int nj = 0; nj < 8; nj++)
#pragma unroll
            for (int e = 0; e < 4; e++) cO[mi][nj][e] = 0.f;
    float m[4], l[4];
#pragma unroll
    for (int i = 0; i < 4; i++) { m[i] = -3.0e38f; l[i] = 0.f; }

    const int nkv = 2 * (qb + 1);
    for (int kb = 0; kb < nkv; kb++) {
        __syncthreads();  // prev-iter readers done with Ks/Vs/Ps
        // ---- Load K, V tiles (64 rows, tf32-rna) ----
        {
            const int row = tid >> 1;
            const int dh = (tid & 1) * 32;
            const float* ksrc = qkv + ((long)(b * TT + kb * 64 + row) * 3 + 1) * 1024 + h * 64 + dh;
            const float* vsrc = qkv + ((long)(b * TT + kb * 64 + row) * 3 + 2) * 1024 + h * 64 + dh;
#pragma unroll
            for (int j = 0; j < 8; j++) {
                float4 v = *(const float4*)(ksrc + j * 4);
                uint4 s;
                s.x = f2tf32(v.x); s.y = f2tf32(v.y); s.z = f2tf32(v.z); s.w = f2tf32(v.w);
                *(uint4*)&Ks[row * KPAD + dh + j * 4] = s;
                v = *(const float4*)(vsrc + j * 4);
                s.x = f2tf32(v.x); s.y = f2tf32(v.y); s.z = f2tf32(v.z); s.w = f2tf32(v.w);
                *(uint4*)&Vs[row * VPAD + dh + j * 4] = s;
            }
        }
        __syncthreads();

        // ---- S = Q @ K^T : 32 rows x 64 cols per warp; B reused over mi ----
        float cS[2][8][4];
#pragma unroll
        for (int mi = 0; mi < 2; mi++)
#pragma unroll
            for (int nj = 0; nj < 8; nj++)
#pragma unroll
                for (int e = 0; e < 4; e++) cS[mi][nj][e] = 0.f;

#pragma unroll
        for (int ks = 0; ks < 8; ks++) {
#pragma unroll
            for (int nj = 0; nj < 8; nj++) {
                uint32_t bb[2];
                int base = (nj * 8 + gid) * KPAD + ks * 8 + tig;
                bb[0] = Ks[base];
                bb[1] = Ks[base + 4];
                mma_tf32(cS[0][nj], qa[ks][0], bb);
                mma_tf32(cS[1][nj], qa[ks][1], bb);
            }
        }

        if (kb >= 2 * qb) {  // tiles intersecting the causal diagonal
#pragma unroll
            for (int mi = 0; mi < 2; mi++) {
                int rA = qb * 128 + r0 + mi * 16 + gid;
                int rB = rA + 8;
#pragma unroll
                for (int nj = 0; nj < 8; nj++) {
                    int col = kb * 64 + nj * 8 + 2 * tig;
                    if (col     > rA) cS[mi][nj][0] = -3.0e38f;
                    if (col + 1 > rA) cS[mi][nj][1] = -3.0e38f;
                    if (col     > rB) cS[mi][nj][2] = -3.0e38f;
                    if (col + 1 > rB) cS[mi][nj][3] = -3.0e38f;
                }
            }
        }

        // ---- Online softmax (4 rows per thread; reduce over 4 tig lanes) ----
        float mx[4] = {-3.0e38f, -3.0e38f, -3.0e38f, -3.0e38f};
#pragma unroll
        for (int mi = 0; mi < 2; mi++)
#pragma unroll
            for (int nj = 0; nj < 8; nj++) {
                mx[mi * 2 + 0] = fmaxf(mx[mi * 2 + 0], fmaxf(cS[mi][nj][0], cS[mi][nj][1]));
                mx[mi * 2 + 1] = fmaxf(mx[mi * 2 + 1], fmaxf(cS[mi][nj][2], cS[mi][nj][3]));
            }
        float al[4], sum[4];
#pragma unroll
        for (int i = 0; i < 4; i++) {
            mx[i] = fmaxf(mx[i], __shfl_xor_sync(0xffffffffu, mx[i], 1));
            mx[i] = fmaxf(mx[i], __shfl_xor_sync(0xffffffffu, mx[i], 2));
            float mn = fmaxf(m[i], mx[i]);
            al[i] = __expf(m[i] - mn);
            m[i] = mn;
            sum[i] = 0.f;
        }
#pragma unroll
        for (int mi = 0; mi < 2; mi++)
#pragma unroll
            for (int nj = 0; nj < 8; nj++) {
                cS[mi][nj][0] = __expf(cS[mi][nj][0] - m[mi * 2 + 0]); sum[mi * 2 + 0] += cS[mi][nj][0];
                cS[mi][nj][1] = __expf(cS[mi][nj][1] - m[mi * 2 + 0]); sum[mi * 2 + 0] += cS[mi][nj][1];
                cS[mi][nj][2] = __expf(cS[mi][nj][2] - m[mi * 2 + 1]); sum[mi * 2 + 1] += cS[mi][nj][2];
                cS[mi][nj][3] = __expf(cS[mi][nj][3] - m[mi * 2 + 1]); sum[mi * 2 + 1] += cS[mi][nj][3];
            }
#pragma unroll
        for (int i = 0; i < 4; i++) {
            sum[i] += __shfl_xor_sync(0xffffffffu, sum[i], 1);
            sum[i] += __shfl_xor_sync(0xffffffffu, sum[i], 2);
            l[i] = l[i] * al[i] + sum[i];
        }
#pragma unroll
        for (int mi = 0; mi < 2; mi++)
#pragma unroll
            for (int nj = 0; nj < 8; nj++) {
                cO[mi][nj][0] *= al[mi * 2 + 0]; cO[mi][nj][1] *= al[mi * 2 + 0];
                cO[mi][nj][2] *= al[mi * 2 + 1]; cO[mi][nj][3] *= al[mi * 2 + 1];
            }

        // ---- Store P (tf32-rna); warp-private rows ----
#pragma unroll
        for (int mi = 0; mi < 2; mi++)
#pragma unroll
            for (int nj = 0; nj < 8; nj++) {
                int col = nj * 8 + 2 * tig;
                uint2 p0 = make_uint2(f2tf32(cS[mi][nj][0]), f2tf32(cS[mi][nj][1]));
                *(uint2*)&Ps[(r0 + mi * 16 + gid) * PPAD + col] = p0;
                uint2 p1 = make_uint2(f2tf32(cS[mi][nj][2]), f2tf32(cS[mi][nj][3]));
                *(uint2*)&Ps[(r0 + mi * 16 + gid + 8) * PPAD + col] = p1;
            }
        __syncwarp();

        // ---- O += P @ V : 32 rows x 64 dims per warp; V reused over mi ----
#pragma unroll
        for (int ks = 0; ks < 8; ks++) {
            uint32_t pa[2][4];
#pragma unroll
            for (int mi = 0; mi < 2; mi++) {
                int abase = (r0 + mi * 16 + gid) * PPAD + ks * 8 + tig;
                pa[mi][0] = Ps[abase];
                pa[mi][1] = Ps[abase + 8 * PPAD];
                pa[mi][2] = Ps[abase + 4];
                pa[mi][3] = Ps[abase + 8 * PPAD + 4];
            }
#pragma unroll
            for (int nj = 0; nj < 8; nj++) {
                uint32_t bb[2];
                int bbase = (ks * 8 + tig) * VPAD + nj * 8 + gid;
                bb[0] = Vs[bbase];
                bb[1] = Vs[bbase + 4 * VPAD];
                mma_tf32(cO[0][nj], pa[0], bb);
                mma_tf32(cO[1][nj], pa[1], bb);
            }
        }
    }

    // ---- Epilogue ----
#pragma unroll
    for (int mi = 0; mi < 2; mi++) {
        float inv0 = 1.0f / l[mi * 2 + 0], inv1 = 1.0f / l[mi * 2 + 1];
        long rowA = (long)(b * TT + qb * 128 + r0 + mi * 16 + gid) * 1024 + h * 64;
        long rowB = rowA + 8 * 1024;
#pragma unroll
        for (int nj = 0; nj < 8; nj++) {
            int col = nj * 8 + 2 * tig;
            *(float2*)(y + rowA + col) = make_float2(cO[mi][nj][0] * inv0, cO[mi][nj][1] * inv0);
            *(float2*)(y + rowB + col) = make_float2(cO[mi][nj][2] * inv1, cO[mi][nj][3] * inv1);
        }
    }
}

// ---------------------------------------------------------------------------
extern "C" void kernel_launch(void* const* d_in, const int* in_sizes, int n_in,
                              void* d_out, int out_size) {
    const float* x      = (const float*)d_in[0];
    const float* cosb   = (const float*)d_in[1];
    const float* sinb   = (const float*)d_in[2];
    const float* W_attn = (const float*)d_in[3];
    const float* b_attn = (const float*)d_in[4];
    const float* W_proj = (const float*)d_in[5];
    const float* b_proj = (const float*)d_in[6];
    float* out = (float*)d_out;

    float *qkv, *y;
    cudaGetSymbolAddress((void**)&qkv, g_qkv);
    cudaGetSymbolAddress((void**)&y, g_y);

    // 1) QKV GEMM (TF32): [4096,1024] @ [1024,3072] + bias
    tf32_gemm_bias<<<dim3(3072 / 128, 4096 / 128), 256>>>(x, W_attn, b_attn, qkv, 4096, 3072, 1024);

    // 2) per-head RMSNorm + RoPE on q,k (in place)
    norm_rope_kernel<<<2 * TT, 256>>>(qkv, cosb, sinb);

    // 3) causal flash attention (TF32, 32-row warp tiles, 128-thread CTAs)
    cudaFuncSetAttribute(attn_tf32_kernel, cudaFuncAttributeMaxDynamicSharedMemorySize, ATT_SMEM);
    attn_tf32_kernel<<<dim3(TT / 128, 16, 2), 128, ATT_SMEM>>>(qkv, y);

    // 4) output projection (TF32): [4096,1024] @ [1024,1024] + bias
    tf32_gemm_bias<<<dim3(1024 / 128, 4096 / 128), 256>>>(y, W_proj, b_proj, out, 4096, 1024, 1024);
}

// round 9
// speedup vs baseline: 1.0730x; 1.0267x over previous
#include <cuda_runtime.h>
#include <cstdint>

// Problem constants: B=2, T=2048, C=1024, H=16, D=64
#define TT 2048

// Scratch (allocation-free rule: __device__ globals)
__device__ float g_qkv[2 * 2048 * 3 * 1024];  // [B,T,3,H,D]
__device__ float g_y[2 * 2048 * 1024];        // [B,T,H,D]

__device__ __forceinline__ uint32_t f2tf32(float f) {
    uint32_t r;
    asm("cvt.rna.tf32.f32 %0, %1;" : "=r"(r) : "f"(f));
    return r;
}

__device__ __forceinline__ void mma_tf32(float* c, const uint32_t* a, const uint32_t* b) {
    asm volatile(
        "mma.sync.aligned.m16n8k8.row.col.f32.tf32.tf32.f32 "
        "{%0,%1,%2,%3}, {%4,%5,%6,%7}, {%8,%9}, {%0,%1,%2,%3};\n"
        : "+f"(c[0]), "+f"(c[1]), "+f"(c[2]), "+f"(c[3])
        : "r"(a[0]), "r"(a[1]), "r"(a[2]), "r"(a[3]), "r"(b[0]), "r"(b[1]));
}

// ---------------------------------------------------------------------------
// TF32 tensor-core GEMM with bias, 2-stage smem double buffer (unchanged).
// ---------------------------------------------------------------------------
#define PADK 20
#define PADN 136

__global__ __launch_bounds__(256, 2)
void tf32_gemm_bias(const float* __restrict__ A, const float* __restrict__ Bw,
                    const float* __restrict__ bias, float* __restrict__ Cout,
                    int M, int N, int K) {
    __shared__ uint32_t As[2][128 * PADK];
    __shared__ uint32_t Bs[2][16 * PADN];

    const int tid = threadIdx.x;
    const int lane = tid & 31;
    const int warp = tid >> 5;
    const int gid = lane >> 2;
    const int tig = lane & 3;
    const int wm = warp >> 1;
    const int wn = warp & 1;
    const int m0w = wm * 32;
    const int n0w = wn * 64;
    const int br = blockIdx.y * 128;
    const int bc = blockIdx.x * 128;

    const int arow = tid >> 2;
    const int akc  = (tid & 3) * 4;
    const int bkr  = tid >> 5;
    const int bnc  = (tid & 31) * 4;

    const float* Ap0 = A + (long)(br + arow) * K + akc;
    const float* Ap1 = A + (long)(br + arow + 64) * K + akc;
    const float* Bp0 = Bw + (long)bkr * N + bc + bnc;
    const float* Bp1 = Bw + (long)(bkr + 8) * N + bc + bnc;

    float c[2][8][4];
#pragma unroll
    for (int mi = 0; mi < 2; mi++)
#pragma unroll
        for (int nj = 0; nj < 8; nj++)
#pragma unroll
            for (int e = 0; e < 4; e++) c[mi][nj][e] = 0.f;

    float4 ag0 = *(const float4*)(Ap0);
    float4 ag1 = *(const float4*)(Ap1);
    float4 bg0 = *(const float4*)(Bp0);
    float4 bg1 = *(const float4*)(Bp1);
    {
        uint4 s;
        s.x = f2tf32(ag0.x); s.y = f2tf32(ag0.y); s.z = f2tf32(ag0.z); s.w = f2tf32(ag0.w);
        *(uint4*)&As[0][arow * PADK + akc] = s;
        s.x = f2tf32(ag1.x); s.y = f2tf32(ag1.y); s.z = f2tf32(ag1.z); s.w = f2tf32(ag1.w);
        *(uint4*)&As[0][(arow + 64) * PADK + akc] = s;
        s.x = f2tf32(bg0.x); s.y = f2tf32(bg0.y); s.z = f2tf32(bg0.z); s.w = f2tf32(bg0.w);
        *(uint4*)&Bs[0][bkr * PADN + bnc] = s;
        s.x = f2tf32(bg1.x); s.y = f2tf32(bg1.y); s.z = f2tf32(bg1.z); s.w = f2tf32(bg1.w);
        *(uint4*)&Bs[0][(bkr + 8) * PADN + bnc] = s;
    }
    __syncthreads();

    int st = 0;
    for (int k0 = 0; k0 < K; k0 += 16) {
        const bool hasNext = (k0 + 16 < K);
        if (hasNext) {
            ag0 = *(const float4*)(Ap0 + k0 + 16);
            ag1 = *(const float4*)(Ap1 + k0 + 16);
            bg0 = *(const float4*)(Bp0 + (long)(k0 + 16) * N);
            bg1 = *(const float4*)(Bp1 + (long)(k0 + 16) * N);
        }

#pragma unroll
        for (int ks = 0; ks < 16; ks += 8) {
            uint32_t a[2][4];
#pragma unroll
            for (int mi = 0; mi < 2; mi++) {
                int base = (m0w + mi * 16 + gid) * PADK + ks + tig;
                a[mi][0] = As[st][base];
                a[mi][1] = As[st][base + 8 * PADK];
                a[mi][2] = As[st][base + 4];
                a[mi][3] = As[st][base + 8 * PADK + 4];
            }
            uint32_t b[8][2];
#pragma unroll
            for (int nj = 0; nj < 8; nj++) {
                int base = (ks + tig) * PADN + n0w + nj * 8 + gid;
                b[nj][0] = Bs[st][base];
                b[nj][1] = Bs[st][base + 4 * PADN];
            }
#pragma unroll
            for (int mi = 0; mi < 2; mi++)
#pragma unroll
                for (int nj = 0; nj < 8; nj++)
                    mma_tf32(c[mi][nj], a[mi], b[nj]);
        }

        if (hasNext) {
            uint4 s;
            s.x = f2tf32(ag0.x); s.y = f2tf32(ag0.y); s.z = f2tf32(ag0.z); s.w = f2tf32(ag0.w);
            *(uint4*)&As[st ^ 1][arow * PADK + akc] = s;
            s.x = f2tf32(ag1.x); s.y = f2tf32(ag1.y); s.z = f2tf32(ag1.z); s.w = f2tf32(ag1.w);
            *(uint4*)&As[st ^ 1][(arow + 64) * PADK + akc] = s;
            s.x = f2tf32(bg0.x); s.y = f2tf32(bg0.y); s.z = f2tf32(bg0.z); s.w = f2tf32(bg0.w);
            *(uint4*)&Bs[st ^ 1][bkr * PADN + bnc] = s;
            s.x = f2tf32(bg1.x); s.y = f2tf32(bg1.y); s.z = f2tf32(bg1.z); s.w = f2tf32(bg1.w);
            *(uint4*)&Bs[st ^ 1][(bkr + 8) * PADN + bnc] = s;
        }
        __syncthreads();
        st ^= 1;
    }

#pragma unroll
    for (int mi = 0; mi < 2; mi++) {
        int row = br + m0w + mi * 16 + gid;
#pragma unroll
        for (int nj = 0; nj < 8; nj++) {
            int col = bc + n0w + nj * 8 + tig * 2;
            float2 bb = *(const float2*)(bias + col);
            float2 o0 = make_float2(c[mi][nj][0] + bb.x, c[mi][nj][1] + bb.y);
            float2 o1 = make_float2(c[mi][nj][2] + bb.x, c[mi][nj][3] + bb.y);
            *(float2*)(Cout + (long)row * N + col) = o0;
            *(float2*)(Cout + (long)(row + 8) * N + col) = o1;
        }
    }
}

// ---------------------------------------------------------------------------
// Fused per-head RMSNorm + RoPE on q and k slots of g_qkv (in place).
// ---------------------------------------------------------------------------
__global__ __launch_bounds__(256)
void norm_rope_kernel(float* __restrict__ qkv,
                      const float* __restrict__ cosb,
                      const float* __restrict__ sinb) {
    __shared__ float qn[1024];
    __shared__ float kn[1024];
    const int bt = blockIdx.x;
    const int t = bt & (TT - 1);
    const int tid = threadIdx.x;
    float* qrow = qkv + (long)bt * 3072;
    float* krow = qrow + 1024;

    float4 qv = *(const float4*)(qrow + tid * 4);
    float4 kv = *(const float4*)(krow + tid * 4);
    float qs = qv.x * qv.x + qv.y * qv.y + qv.z * qv.z + qv.w * qv.w;
    float ks = kv.x * kv.x + kv.y * kv.y + kv.z * kv.z + kv.w * kv.w;
#pragma unroll
    for (int o = 8; o > 0; o >>= 1) {
        qs += __shfl_xor_sync(0xffffffffu, qs, o);
        ks += __shfl_xor_sync(0xffffffffu, ks, o);
    }
    const float qsc = rsqrtf(qs * (1.f / 64.f) + 1.1920929e-07f);
    const float ksc = rsqrtf(ks * (1.f / 64.f) + 1.1920929e-07f);
    float4 qn4 = make_float4(qv.x * qsc, qv.y * qsc, qv.z * qsc, qv.w * qsc);
    float4 kn4 = make_float4(kv.x * ksc, kv.y * ksc, kv.z * ksc, kv.w * ksc);
    *(float4*)&qn[tid * 4] = qn4;
    *(float4*)&kn[tid * 4] = kn4;
    __syncthreads();

    const int i = tid * 4;
    const int d = i & 63;
    const int base = i - d;
    float4 cv = *(const float4*)(cosb + t * 64 + d);
    float4 sv = *(const float4*)(sinb + t * 64 + d);
    float4 rq, rk;
    if (d < 32) {
        float4 pq = *(const float4*)&qn[base + d + 32];
        float4 pk = *(const float4*)&kn[base + d + 32];
        rq = make_float4(-pq.x, -pq.y, -pq.z, -pq.w);
        rk = make_float4(-pk.x, -pk.y, -pk.z, -pk.w);
    } else {
        rq = *(const float4*)&qn[base + d - 32];
        rk = *(const float4*)&kn[base + d - 32];
    }
    float4 oq, ok;
    oq.x = qn4.x * cv.x + rq.x * sv.x;  oq.y = qn4.y * cv.y + rq.y * sv.y;
    oq.z = qn4.z * cv.z + rq.z * sv.z;  oq.w = qn4.w * cv.w + rq.w * sv.w;
    ok.x = kn4.x * cv.x + rk.x * sv.x;  ok.y = kn4.y * cv.y + rk.y * sv.y;
    ok.z = kn4.z * cv.z + rk.z * sv.z;  ok.w = kn4.w * cv.w + rk.w * sv.w;
    *(float4*)(qrow + i) = oq;
    *(float4*)(krow + i) = ok;
}

// ---------------------------------------------------------------------------
// TF32 flash attention with FIXED-MAX softmax.
// After rms_norm, ||q||=||k||=8 and Q is pre-scaled by 1/8, so |s| <= 8
// (Cauchy-Schwarz). Softmax is shift-invariant -> use constant max m=8:
// p = exp(s-8) in [e^-16, 1]. No running max, no rescaling, row-sum
// accumulated per-thread and reduced once at the end.
// Config: round-6 best (256 thr, 8 warps, 16 rows/warp, BKV=64, 2 CTA/SM).
// ---------------------------------------------------------------------------
#define KPAD 68    // K frag lanes: 4*gid + tig -> all 32 banks
#define VPAD 72    // V frag lanes: 8*tig + gid -> all 32 banks
#define PPAD 68
#define ATT_SMEM ((64 * KPAD + 64 * VPAD + 128 * PPAD) * 4)

__global__ __launch_bounds__(256, 2)
void attn_tf32_kernel(const float* __restrict__ qkv, float* __restrict__ y) {
    extern __shared__ uint32_t smu[];
    uint32_t* Ks = smu;                 // [64][KPAD]
    uint32_t* Vs = Ks + 64 * KPAD;      // [64][VPAD]
    uint32_t* Ps = Vs + 64 * VPAD;      // [128][PPAD]; also Q staging

    const int qb = (int)(gridDim.x - 1) - (int)blockIdx.x;  // heavy CTAs first
    const int h = blockIdx.y, b = blockIdx.z;
    const int tid = threadIdx.x;
    const int lane = tid & 31, warp = tid >> 5;
    const int gid = lane >> 2, tig = lane & 3;
    const int r0 = warp * 16;

    // ---- Stage Q (scaled, tf32-rna) into Ps, then load A-fragments ----
    {
        const int row = tid >> 1;
        const int dh = (tid & 1) * 32;
        const float* src = qkv + ((long)(b * TT + qb * 128 + row) * 3) * 1024 + h * 64 + dh;
#pragma unroll
        for (int j = 0; j < 8; j++) {
            float4 v = *(const float4*)(src + j * 4);
            uint4 s;
            s.x = f2tf32(v.x * 0.125f); s.y = f2tf32(v.y * 0.125f);
            s.z = f2tf32(v.z * 0.125f); s.w = f2tf32(v.w * 0.125f);
            *(uint4*)&Ps[row * PPAD + dh + j * 4] = s;
        }
    }
    __syncthreads();
    uint32_t qa[8][4];
#pragma unroll
    for (int ks = 0; ks < 8; ks++) {
        int base = (r0 + gid) * PPAD + ks * 8 + tig;
        qa[ks][0] = Ps[base];
        qa[ks][1] = Ps[base + 8 * PPAD];
        qa[ks][2] = Ps[base + 4];
        qa[ks][3] = Ps[base + 8 * PPAD + 4];
    }

    float cO[8][4];
#pragma unroll
    for (int nj = 0; nj < 8; nj++)
#pragma unroll
        for (int e = 0; e < 4; e++) cO[nj][e] = 0.f;
    float lp0 = 0.f, lp1 = 0.f;   // per-thread partial row sums (reduced at end)

    const int nkv = 2 * (qb + 1);
    for (int kb = 0; kb < nkv; kb++) {
        __syncthreads();  // prev-iter readers done with Ks/Vs/Ps
        // ---- Load K, V tiles (64 rows, tf32-rna) ----
        {
            const int row = tid >> 2;
            const int dh = (tid & 3) * 16;
            const float* ksrc = qkv + ((long)(b * TT + kb * 64 + row) * 3 + 1) * 1024 + h * 64 + dh;
            const float* vsrc = qkv + ((long)(b * TT + kb * 64 + row) * 3 + 2) * 1024 + h * 64 + dh;
#pragma unroll
            for (int j = 0; j < 4; j++) {
                float4 v = *(const float4*)(ksrc + j * 4);
                uint4 s;
                s.x = f2tf32(v.x); s.y = f2tf32(v.y); s.z = f2tf32(v.z); s.w = f2tf32(v.w);
                *(uint4*)&Ks[row * KPAD + dh + j * 4] = s;
                v = *(const float4*)(vsrc + j * 4);
                s.x = f2tf32(v.x); s.y = f2tf32(v.y); s.z = f2tf32(v.z); s.w = f2tf32(v.w);
                *(uint4*)&Vs[row * VPAD + dh + j * 4] = s;
            }
        }
        __syncthreads();

        // ---- S = Q @ K^T : warp computes 16 rows x 64 cols (8 n-tiles) ----
        float cS[8][4];
#pragma unroll
        for (int nj = 0; nj < 8; nj++)
#pragma unroll
            for (int e = 0; e < 4; e++) cS[nj][e] = 0.f;

#pragma unroll
        for (int ks = 0; ks < 8; ks++) {
#pragma unroll
            for (int nj = 0; nj < 8; nj++) {
                uint32_t bb[2];
                int base = (nj * 8 + gid) * KPAD + ks * 8 + tig;
                bb[0] = Ks[base];
                bb[1] = Ks[base + 4];
                mma_tf32(cS[nj], qa[ks], bb);
            }
        }

        if (kb >= 2 * qb) {  // tiles intersecting the causal diagonal
            int rA = qb * 128 + r0 + gid;
            int rB = rA + 8;
#pragma unroll
            for (int nj = 0; nj < 8; nj++) {
                int col = kb * 64 + nj * 8 + 2 * tig;
                if (col     > rA) cS[nj][0] = -3.0e38f;
                if (col + 1 > rA) cS[nj][1] = -3.0e38f;
                if (col     > rB) cS[nj][2] = -3.0e38f;
                if (col + 1 > rB) cS[nj][3] = -3.0e38f;
            }
        }

        // ---- Fixed-max softmax: p = exp(s - 8); accumulate partial sums ----
#pragma unroll
        for (int nj = 0; nj < 8; nj++) {
            cS[nj][0] = __expf(cS[nj][0] - 8.0f); lp0 += cS[nj][0];
            cS[nj][1] = __expf(cS[nj][1] - 8.0f); lp0 += cS[nj][1];
            cS[nj][2] = __expf(cS[nj][2] - 8.0f); lp1 += cS[nj][2];
            cS[nj][3] = __expf(cS[nj][3] - 8.0f); lp1 += cS[nj][3];
        }

        // ---- Store P (tf32-rna); warp-private rows ----
#pragma unroll
        for (int nj = 0; nj < 8; nj++) {
            int col = nj * 8 + 2 * tig;
            uint2 p0 = make_uint2(f2tf32(cS[nj][0]), f2tf32(cS[nj][1]));
            *(uint2*)&Ps[(r0 + gid) * PPAD + col] = p0;
            uint2 p1 = make_uint2(f2tf32(cS[nj][2]), f2tf32(cS[nj][3]));
            *(uint2*)&Ps[(r0 + gid + 8) * PPAD + col] = p1;
        }
        __syncwarp();

        // ---- O += P @ V : 16 rows x 64 dims (8 n-tiles), 8 k-steps ----
#pragma unroll
        for (int ks = 0; ks < 8; ks++) {
            uint32_t pa[4];
            int abase = (r0 + gid) * PPAD + ks * 8 + tig;
            pa[0] = Ps[abase];
            pa[1] = Ps[abase + 8 * PPAD];
            pa[2] = Ps[abase + 4];
            pa[3] = Ps[abase + 8 * PPAD + 4];
#pragma unroll
            for (int nj = 0; nj < 8; nj++) {
                uint32_t bb[2];
                int bbase = (ks * 8 + tig) * VPAD + nj * 8 + gid;
                bb[0] = Vs[bbase];
                bb[1] = Vs[bbase + 4 * VPAD];
                mma_tf32(cO[nj], pa, bb);
            }
        }
    }

    // ---- Final row-sum reduction (once) + epilogue ----
    lp0 += __shfl_xor_sync(0xffffffffu, lp0, 1);
    lp0 += __shfl_xor_sync(0xffffffffu, lp0, 2);
    lp1 += __shfl_xor_sync(0xffffffffu, lp1, 1);
    lp1 += __shfl_xor_sync(0xffffffffu, lp1, 2);
    float inv0 = 1.0f / lp0, inv1 = 1.0f / lp1;
    long rowA = (long)(b * TT + qb * 128 + r0 + gid) * 1024 + h * 64;
    long rowB = rowA + 8 * 1024;
#pragma unroll
    for (int nj = 0; nj < 8; nj++) {
        int col = nj * 8 + 2 * tig;
        *(float2*)(y + rowA + col) = make_float2(cO[nj][0] * inv0, cO[nj][1] * inv0);
        *(float2*)(y + rowB + col) = make_float2(cO[nj][2] * inv1, cO[nj][3] * inv1);
    }
}

// ---------------------------------------------------------------------------
extern "C" void kernel_launch(void* const* d_in, const int* in_sizes, int n_in,
                              void* d_out, int out_size) {
    const float* x      = (const float*)d_in[0];
    const float* cosb   = (const float*)d_in[1];
    const float* sinb   = (const float*)d_in[2];
    const float* W_attn = (const float*)d_in[3];
    const float* b_attn = (const float*)d_in[4];
    const float* W_proj = (const float*)d_in[5];
    const float* b_proj = (const float*)d_in[6];
    float* out = (float*)d_out;

    float *qkv, *y;
    cudaGetSymbolAddress((void**)&qkv, g_qkv);
    cudaGetSymbolAddress((void**)&y, g_y);

    // 1) QKV GEMM (TF32): [4096,1024] @ [1024,3072] + bias
    tf32_gemm_bias<<<dim3(3072 / 128, 4096 / 128), 256>>>(x, W_attn, b_attn, qkv, 4096, 3072, 1024);

    // 2) per-head RMSNorm + RoPE on q,k (in place)
    norm_rope_kernel<<<2 * TT, 256>>>(qkv, cosb, sinb);

    // 3) causal flash attention (TF32, fixed-max softmax)
    cudaFuncSetAttribute(attn_tf32_kernel, cudaFuncAttributeMaxDynamicSharedMemorySize, ATT_SMEM);
    attn_tf32_kernel<<<dim3(TT / 128, 16, 2), 256, ATT_SMEM>>>(qkv, y);

    // 4) output projection (TF32): [4096,1024] @ [1024,1024] + bias
    tf32_gemm_bias<<<dim3(1024 / 128, 4096 / 128), 256>>>(y, W_proj, b_proj, out, 4096, 1024, 1024);
}